// round 11
// baseline (speedup 1.0000x reference)
#include <cuda_runtime.h>
#include <cuda_bf16.h>
#include <math.h>
#include <cstdint>

#define N_TOK_MAX 11136
#define IN_DIM    256
#define E_DIM     256
#define NHEAD     8
#define HDIM      32
#define NB        16
#define QKV_DIM   768

typedef unsigned int u32;

// Split-format tensors: each element stored as uint2 (tf32_hi, tf32_lo).
__device__ uint2 g_xsp[(size_t)N_TOK_MAX * IN_DIM];
__device__ uint2 g_wqkv_sp[QKV_DIM * IN_DIM];
__device__ uint2 g_ow_sp[E_DIM * E_DIM];
__device__ uint2 g_qkvsp[(size_t)N_TOK_MAX * QKV_DIM];
__device__ uint2 g_attsp[(size_t)N_TOK_MAX * E_DIM];
__device__ int   g_start[NB + 1];

// ---- tf32 helpers -----------------------------------------------------------
__device__ __forceinline__ void split_tf32(float v, u32& hi, u32& lo) {
    asm("cvt.rna.tf32.f32 %0, %1;" : "=r"(hi) : "f"(v));
    float r = v - __uint_as_float(hi);
    asm("cvt.rna.tf32.f32 %0, %1;" : "=r"(lo) : "f"(r));
}

__device__ __forceinline__ void mma8(float* c, const u32* a, u32 b0, u32 b1) {
    asm volatile(
        "mma.sync.aligned.m16n8k8.row.col.f32.tf32.tf32.f32 "
        "{%0,%1,%2,%3}, {%4,%5,%6,%7}, {%8,%9}, {%0,%1,%2,%3};"
        : "+f"(c[0]), "+f"(c[1]), "+f"(c[2]), "+f"(c[3])
        : "r"(a[0]), "r"(a[1]), "r"(a[2]), "r"(a[3]), "r"(b0), "r"(b1));
}

// 3xTF32: C += Ahi*Bhi + Ahi*Blo + Alo*Bhi
__device__ __forceinline__ void mma3(float* c, const u32* ah, const u32* al,
                                     u32 bh0, u32 bh1, u32 bl0, u32 bl1) {
    mma8(c, ah, bh0, bh1);
    mma8(c, ah, bl0, bl1);
    mma8(c, al, bh0, bh1);
}

// ---------------------------------------------------------------------------
// Kernel 0: split fp32 -> (tf32_hi, tf32_lo) uint2
// ---------------------------------------------------------------------------
__global__ void split_kernel(const float* __restrict__ s, uint2* __restrict__ d, int n) {
    for (int i = blockIdx.x * blockDim.x + threadIdx.x; i < n;
         i += gridDim.x * blockDim.x) {
        u32 hi, lo;
        split_tf32(s[i], hi, lo);
        d[i] = make_uint2(hi, lo);
    }
}

// ---------------------------------------------------------------------------
// Kernel 1: histogram of sorted batch ids -> segment start offsets
// ---------------------------------------------------------------------------
__global__ void hist_kernel(const int* __restrict__ ids, int n) {
    __shared__ int cnt[NB];
    int t = threadIdx.x;
    if (t < NB) cnt[t] = 0;
    __syncthreads();
    for (int i = t; i < n; i += blockDim.x)
        atomicAdd(&cnt[ids[i]], 1);
    __syncthreads();
    if (t == 0) {
        int acc = 0;
        for (int v = 0; v < NB; v++) { g_start[v] = acc; acc += cnt[v]; }
        g_start[NB] = acc;
    }
}

// ---------------------------------------------------------------------------
// 3xTF32 GEMM on pre-split inputs: C = A[M,K] @ B[N,K]^T + bias
// 64x64 tile, 128 threads (R6-best shape). No split ALU in mainloop.
// SPLIT_OUT: write C as split uint2 (for downstream consumers) vs fp32.
// ---------------------------------------------------------------------------
template<bool SPLIT_OUT>
__global__ __launch_bounds__(128) void mma_gemm_sp(
    const uint2* __restrict__ A, const uint2* __restrict__ B,
    const float* __restrict__ bias, void* __restrict__ Cout,
    int M, int N, int K)
{
    __shared__ uint2 As[64][36];
    __shared__ uint2 Bs[64][36];

    const int t    = threadIdx.x;
    const int lane = t & 31, w = t >> 5;
    const int g    = lane >> 2, tig = lane & 3;
    const int m0   = blockIdx.y * 64;
    const int n0   = blockIdx.x * 64;

    float acc[8][4];
#pragma unroll
    for (int i = 0; i < 8; i++)
#pragma unroll
        for (int j = 0; j < 4; j++) acc[i][j] = 0.f;

    const int lr = t >> 1, lc = (t & 1) * 16;   // loader: row, 16-elt slab

    for (int kc = 0; kc < K; kc += 32) {
        {
            int ga = min(m0 + lr, M - 1);
            const uint4* ap = (const uint4*)(A + (size_t)ga * K + kc + lc);
            const uint4* bp = (const uint4*)(B + (size_t)(n0 + lr) * K + kc + lc);
#pragma unroll
            for (int q = 0; q < 8; q++) {
                *(uint4*)&As[lr][lc + q * 2] = ap[q];
                *(uint4*)&Bs[lr][lc + q * 2] = bp[q];
            }
        }
        __syncthreads();

#pragma unroll
        for (int ks = 0; ks < 4; ks++) {
            const int k0 = ks * 8;
            uint2 a0 = As[16 * w + g][k0 + tig];
            uint2 a1 = As[16 * w + g + 8][k0 + tig];
            uint2 a2 = As[16 * w + g][k0 + tig + 4];
            uint2 a3 = As[16 * w + g + 8][k0 + tig + 4];
            u32 ah[4] = {a0.x, a1.x, a2.x, a3.x};
            u32 al[4] = {a0.y, a1.y, a2.y, a3.y};
#pragma unroll
            for (int nt = 0; nt < 8; nt++) {
                uint2 b0 = Bs[nt * 8 + g][k0 + tig];
                uint2 b1 = Bs[nt * 8 + g][k0 + tig + 4];
                mma3(acc[nt], ah, al, b0.x, b1.x, b0.y, b1.y);
            }
        }
        __syncthreads();
    }

    const int ra = m0 + 16 * w + g;
    const int rb = ra + 8;
#pragma unroll
    for (int nt = 0; nt < 8; nt++) {
        int col = n0 + nt * 8 + 2 * tig;
        float b0 = bias[col], b1 = bias[col + 1];
        float v00 = acc[nt][0] + b0, v01 = acc[nt][1] + b1;
        float v10 = acc[nt][2] + b0, v11 = acc[nt][3] + b1;
        if (SPLIT_OUT) {
            uint2* C = (uint2*)Cout;
            u32 hi, lo;
            if (ra < M) {
                split_tf32(v00, hi, lo); C[(size_t)ra * N + col]     = make_uint2(hi, lo);
                split_tf32(v01, hi, lo); C[(size_t)ra * N + col + 1] = make_uint2(hi, lo);
            }
            if (rb < M) {
                split_tf32(v10, hi, lo); C[(size_t)rb * N + col]     = make_uint2(hi, lo);
                split_tf32(v11, hi, lo); C[(size_t)rb * N + col + 1] = make_uint2(hi, lo);
            }
        } else {
            float* C = (float*)Cout;
            if (ra < M) {
                C[(size_t)ra * N + col]     = v00;
                C[(size_t)ra * N + col + 1] = v01;
            }
            if (rb < M) {
                C[(size_t)rb * N + col]     = v10;
                C[(size_t)rb * N + col + 1] = v11;
            }
        }
    }
}

// ---------------------------------------------------------------------------
// Kernel 3: varlen flash attention, 3xTF32 mma on pre-split K/V (uint2 smem).
// Block = (64-query tile, segment, head). 128 threads, 4 warps (R6 shape).
// Q fragments pre-split in registers (loaded once from g_qkvsp).
// PV reuses S fragments via even/odd V-row permute. Output written split.
// ---------------------------------------------------------------------------
__global__ __launch_bounds__(128) void attn_mma_kernel(int n) {
    const int seg = blockIdx.y;
    const int h   = blockIdx.z;
    const int qs  = g_start[seg];
    const int qe  = g_start[seg + 1];
    const int q0  = qs + blockIdx.x * 64;
    if (q0 >= qe) return;

    __shared__ uint2 Ks[64][36];
    __shared__ uint2 Vp[64][36];   // V rows permuted even-then-odd per 8-group

    const int t    = threadIdx.x;
    const int lane = t & 31, w = t >> 5;
    const int g    = lane >> 2, tig = lane & 3;

    const uint2* __restrict__ qkv = g_qkvsp;
    const int qoff = h * 96;
    const int koff = h * 96 + 32;
    const int voff = h * 96 + 64;

    // Q fragments: split once, straight from global (no smem tile)
    u32 qh[4][4], ql[4][4];
    {
        int ra = min(q0 + 16 * w + g, qe - 1);
        int rb = min(q0 + 16 * w + g + 8, qe - 1);
        const uint2* pa = qkv + (size_t)ra * QKV_DIM + qoff;
        const uint2* pb = qkv + (size_t)rb * QKV_DIM + qoff;
#pragma unroll
        for (int ks = 0; ks < 4; ks++) {
            uint2 v;
            v = pa[ks * 8 + tig];     qh[ks][0] = v.x; ql[ks][0] = v.y;
            v = pb[ks * 8 + tig];     qh[ks][1] = v.x; ql[ks][1] = v.y;
            v = pa[ks * 8 + tig + 4]; qh[ks][2] = v.x; ql[ks][2] = v.y;
            v = pb[ks * 8 + tig + 4]; qh[ks][3] = v.x; ql[ks][3] = v.y;
        }
    }

    // K/V loader: row = t>>1 (0..63), 16-elt slab
    const int lr = t >> 1, lc = (t & 1) * 16;
    const int i8 = lr & 7;
    const int pr = (lr & ~7) | ((i8 & 1) ? 4 + (i8 >> 1) : (i8 >> 1));

    float m_a = -1e30f, m_b = -1e30f;
    float l_a = 0.f, l_b = 0.f;
    float out[4][4];
#pragma unroll
    for (int i = 0; i < 4; i++)
#pragma unroll
        for (int j = 0; j < 4; j++) out[i][j] = 0.f;

    const float scale = 0.17677669529663687f;   // 1/sqrt(32)

    for (int j0 = qs; j0 < qe; j0 += 64) {
        const int nk = min(64, qe - j0);
        // K + permuted-V chunk load (already split in gmem)
        {
            int row = min(j0 + lr, qe - 1);
            const uint4* kp = (const uint4*)(qkv + (size_t)row * QKV_DIM + koff + lc);
            const uint4* vp = (const uint4*)(qkv + (size_t)row * QKV_DIM + voff + lc);
#pragma unroll
            for (int q = 0; q < 8; q++) {
                *(uint4*)&Ks[lr][lc + q * 2] = kp[q];
                *(uint4*)&Vp[pr][lc + q * 2] = vp[q];
            }
        }
        __syncthreads();

        // ---- S = Q @ K^T (3xTF32), 8 key-tiles ----
        float S[8][4];
#pragma unroll
        for (int i = 0; i < 8; i++)
#pragma unroll
            for (int j = 0; j < 4; j++) S[i][j] = 0.f;

#pragma unroll
        for (int ks = 0; ks < 4; ks++) {
            const int k0 = ks * 8;
#pragma unroll
            for (int nt = 0; nt < 8; nt++) {
                uint2 b0 = Ks[nt * 8 + g][k0 + tig];
                uint2 b1 = Ks[nt * 8 + g][k0 + tig + 4];
                mma3(S[nt], qh[ks], ql[ks], b0.x, b1.x, b0.y, b1.y);
            }
        }

        // scale + key mask
#pragma unroll
        for (int nt = 0; nt < 8; nt++) {
            int c0 = nt * 8 + 2 * tig;
            bool ok0 = c0 < nk, ok1 = (c0 + 1) < nk;
            S[nt][0] = ok0 ? S[nt][0] * scale : -1e30f;
            S[nt][1] = ok1 ? S[nt][1] * scale : -1e30f;
            S[nt][2] = ok0 ? S[nt][2] * scale : -1e30f;
            S[nt][3] = ok1 ? S[nt][3] * scale : -1e30f;
        }

        // row max
        float ca = -1e30f, cb = -1e30f;
#pragma unroll
        for (int nt = 0; nt < 8; nt++) {
            ca = fmaxf(ca, fmaxf(S[nt][0], S[nt][1]));
            cb = fmaxf(cb, fmaxf(S[nt][2], S[nt][3]));
        }
#pragma unroll
        for (int d = 1; d <= 2; d <<= 1) {
            ca = fmaxf(ca, __shfl_xor_sync(0xffffffffu, ca, d));
            cb = fmaxf(cb, __shfl_xor_sync(0xffffffffu, cb, d));
        }
        float mn_a = fmaxf(m_a, ca);
        float mn_b = fmaxf(m_b, cb);
        float sf_a = __expf(m_a - mn_a);
        float sf_b = __expf(m_b - mn_b);
        m_a = mn_a; m_b = mn_b;

        // P = exp(S - m), partial row sums
        float sa = 0.f, sb = 0.f;
#pragma unroll
        for (int nt = 0; nt < 8; nt++) {
            S[nt][0] = __expf(S[nt][0] - mn_a);
            S[nt][1] = __expf(S[nt][1] - mn_a);
            S[nt][2] = __expf(S[nt][2] - mn_b);
            S[nt][3] = __expf(S[nt][3] - mn_b);
            sa += S[nt][0] + S[nt][1];
            sb += S[nt][2] + S[nt][3];
        }
#pragma unroll
        for (int d = 1; d <= 2; d <<= 1) {
            sa += __shfl_xor_sync(0xffffffffu, sa, d);
            sb += __shfl_xor_sync(0xffffffffu, sb, d);
        }
        l_a = l_a * sf_a + sa;
        l_b = l_b * sf_b + sb;
#pragma unroll
        for (int nt = 0; nt < 4; nt++) {
            out[nt][0] *= sf_a; out[nt][1] *= sf_a;
            out[nt][2] *= sf_b; out[nt][3] *= sf_b;
        }

        // ---- out += P @ V (3xTF32). A-frags = S-frags directly
        //   (valid because Vp rows are even/odd-permuted per 8-group).
#pragma unroll
        for (int kt = 0; kt < 8; kt++) {
            u32 ah[4], al[4];
            split_tf32(S[kt][0], ah[0], al[0]);
            split_tf32(S[kt][2], ah[1], al[1]);
            split_tf32(S[kt][1], ah[2], al[2]);
            split_tf32(S[kt][3], ah[3], al[3]);
#pragma unroll
            for (int nt = 0; nt < 4; nt++) {
                uint2 b0 = Vp[kt * 8 + tig][nt * 8 + g];
                uint2 b1 = Vp[kt * 8 + tig + 4][nt * 8 + g];
                mma3(out[nt], ah, al, b0.x, b1.x, b0.y, b1.y);
            }
        }
        __syncthreads();   // before next chunk overwrites Ks/Vp
    }

    const float inv_a = 1.0f / l_a;
    const float inv_b = 1.0f / l_b;
    const int ra = q0 + 16 * w + g;
    const int rb = ra + 8;
#pragma unroll
    for (int nt = 0; nt < 4; nt++) {
        int d = nt * 8 + 2 * tig;
        u32 hi, lo;
        if (ra < qe) {
            uint2* p = g_attsp + (size_t)ra * E_DIM + h * HDIM + d;
            split_tf32(out[nt][0] * inv_a, hi, lo); p[0] = make_uint2(hi, lo);
            split_tf32(out[nt][1] * inv_a, hi, lo); p[1] = make_uint2(hi, lo);
        }
        if (rb < qe) {
            uint2* p = g_attsp + (size_t)rb * E_DIM + h * HDIM + d;
            split_tf32(out[nt][2] * inv_b, hi, lo); p[0] = make_uint2(hi, lo);
            split_tf32(out[nt][3] * inv_b, hi, lo); p[1] = make_uint2(hi, lo);
        }
    }
}

// ---------------------------------------------------------------------------
extern "C" void kernel_launch(void* const* d_in, const int* in_sizes, int n_in,
                              void* d_out, int out_size) {
    const float* x      = (const float*)d_in[0];
    const int*   ids    = (const int*)  d_in[1];
    const float* qkv_w  = (const float*)d_in[2];
    const float* qkv_b  = (const float*)d_in[3];
    const float* o_w    = (const float*)d_in[4];
    const float* o_b    = (const float*)d_in[5];
    float*       out    = (float*)d_out;
    const int n = in_sizes[1];   // token count

    uint2 *xsp, *wqkv, *ow, *qkvsp, *attsp;
    cudaGetSymbolAddress((void**)&xsp,   g_xsp);
    cudaGetSymbolAddress((void**)&wqkv,  g_wqkv_sp);
    cudaGetSymbolAddress((void**)&ow,    g_ow_sp);
    cudaGetSymbolAddress((void**)&qkvsp, g_qkvsp);
    cudaGetSymbolAddress((void**)&attsp, g_attsp);

    hist_kernel<<<1, 256>>>(ids, n);

    // pre-split inputs/weights to (hi,lo) format
    int nx = n * IN_DIM;
    split_kernel<<<(nx + 511) / 512, 512>>>(x, xsp, nx);
    split_kernel<<<(QKV_DIM * IN_DIM + 511) / 512, 512>>>(qkv_w, wqkv, QKV_DIM * IN_DIM);
    split_kernel<<<(E_DIM * E_DIM + 511) / 512, 512>>>(o_w, ow, E_DIM * E_DIM);

    dim3 g_qkv_grid(QKV_DIM / 64, (n + 63) / 64);
    mma_gemm_sp<true><<<g_qkv_grid, 128>>>(xsp, wqkv, qkv_b, qkvsp, n, QKV_DIM, IN_DIM);

    dim3 g_attn((n + 63) / 64, NB, NHEAD);
    attn_mma_kernel<<<g_attn, 128>>>(n);

    dim3 g_proj(E_DIM / 64, (n + 63) / 64);
    mma_gemm_sp<false><<<g_proj, 128>>>(attsp, ow, o_b, out, n, E_DIM, E_DIM);
}

// round 12
// speedup vs baseline: 2.4440x; 2.4440x over previous
#include <cuda_runtime.h>
#include <cuda_bf16.h>
#include <math.h>
#include <cstdint>

#define N_TOK_MAX 11136
#define IN_DIM    256
#define E_DIM     256
#define NHEAD     8
#define HDIM      32
#define NB        16
#define QKV_DIM   768

typedef unsigned int u32;

// Scratch (device globals: allocation-free rule)
__device__ float g_qkv[(size_t)N_TOK_MAX * QKV_DIM];   // [N, 768]
__device__ float g_att[(size_t)N_TOK_MAX * E_DIM];     // [N, 256]
__device__ int   g_start[NB + 1];

// ---- bf16 3x-compensation helpers ------------------------------------------
// Split two fp32 (v0 = lower-k elem, v1 = upper) into packed bf16x2 hi + lo.
__device__ __forceinline__ void split2(float v0, float v1, u32& hi, u32& lo) {
    asm("cvt.rn.bf16x2.f32 %0, %1, %2;" : "=r"(hi) : "f"(v1), "f"(v0));
    float f0 = __uint_as_float(hi << 16);
    float f1 = __uint_as_float(hi & 0xffff0000u);
    asm("cvt.rn.bf16x2.f32 %0, %1, %2;" : "=r"(lo) : "f"(v1 - f1), "f"(v0 - f0));
}

__device__ __forceinline__ void mma16(float* c, const u32* a, u32 b0, u32 b1) {
    asm volatile(
        "mma.sync.aligned.m16n8k16.row.col.f32.bf16.bf16.f32 "
        "{%0,%1,%2,%3}, {%4,%5,%6,%7}, {%8,%9}, {%0,%1,%2,%3};"
        : "+f"(c[0]), "+f"(c[1]), "+f"(c[2]), "+f"(c[3])
        : "r"(a[0]), "r"(a[1]), "r"(a[2]), "r"(a[3]), "r"(b0), "r"(b1));
}

// 3x-bf16: C += Ahi*Bhi + Ahi*Blo + Alo*Bhi
__device__ __forceinline__ void mma3(float* c, const u32* ah, const u32* al,
                                     u32 bh0, u32 bh1, u32 bl0, u32 bl1) {
    mma16(c, ah, bh0, bh1);
    mma16(c, ah, bl0, bl1);
    mma16(c, al, bh0, bh1);
}

// ---------------------------------------------------------------------------
// Kernel 1: histogram of sorted batch ids -> segment start offsets
// ---------------------------------------------------------------------------
__global__ void hist_kernel(const int* __restrict__ ids, int n) {
    __shared__ int cnt[NB];
    int t = threadIdx.x;
    if (t < NB) cnt[t] = 0;
    __syncthreads();
    for (int i = t; i < n; i += blockDim.x)
        atomicAdd(&cnt[ids[i]], 1);
    __syncthreads();
    if (t == 0) {
        int acc = 0;
        for (int v = 0; v < NB; v++) { g_start[v] = acc; acc += cnt[v]; }
        g_start[NB] = acc;
    }
}

// ---------------------------------------------------------------------------
// 3x-bf16 MMA GEMM: C[M,N] = A[M,K] @ B[N,K]^T + bias[N]
// 64x64 tile, 128 threads (R6-best shape). Split at load into packed
// k-pair bf16x2 hi/lo smem (same bytes as fp32). Zero split ALU in mainloop.
// ---------------------------------------------------------------------------
__global__ __launch_bounds__(128) void bf16_gemm_kernel(
    const float* __restrict__ A, const float* __restrict__ Bw,
    const float* __restrict__ bias, float* __restrict__ C,
    int M, int N, int K)
{
    __shared__ u32 Ah[64][20], Al[64][20];   // [row][k-pair], stride 20 (conflict-free)
    __shared__ u32 Bh[64][20], Bl[64][20];

    const int t    = threadIdx.x;
    const int lane = t & 31, w = t >> 5;
    const int g    = lane >> 2, tig = lane & 3;
    const int m0   = blockIdx.y * 64;
    const int n0   = blockIdx.x * 64;

    float acc[8][4];
#pragma unroll
    for (int i = 0; i < 8; i++)
#pragma unroll
        for (int j = 0; j < 4; j++) acc[i][j] = 0.f;

    const int lr  = t >> 1;           // row 0..63
    const int kps = (t & 1) * 8;      // k-pair slab base (8 pairs = 16 floats)

    for (int kc = 0; kc < K; kc += 32) {
        {
            int ga = min(m0 + lr, M - 1);
            const float* ap = A  + (size_t)ga * K + kc + (t & 1) * 16;
            const float* bp = Bw + (size_t)(n0 + lr) * K + kc + (t & 1) * 16;
#pragma unroll
            for (int q = 0; q < 4; q++) {
                float4 va = *(const float4*)(ap + q * 4);
                float4 vb = *(const float4*)(bp + q * 4);
                split2(va.x, va.y, Ah[lr][kps + 2 * q],     Al[lr][kps + 2 * q]);
                split2(va.z, va.w, Ah[lr][kps + 2 * q + 1], Al[lr][kps + 2 * q + 1]);
                split2(vb.x, vb.y, Bh[lr][kps + 2 * q],     Bl[lr][kps + 2 * q]);
                split2(vb.z, vb.w, Bh[lr][kps + 2 * q + 1], Bl[lr][kps + 2 * q + 1]);
            }
        }
        __syncthreads();

#pragma unroll
        for (int s = 0; s < 2; s++) {        // two k16 steps per 32-chunk
            const int kp = s * 8;
            u32 ah[4] = {Ah[16 * w + g][kp + tig],     Ah[16 * w + g + 8][kp + tig],
                         Ah[16 * w + g][kp + tig + 4], Ah[16 * w + g + 8][kp + tig + 4]};
            u32 al[4] = {Al[16 * w + g][kp + tig],     Al[16 * w + g + 8][kp + tig],
                         Al[16 * w + g][kp + tig + 4], Al[16 * w + g + 8][kp + tig + 4]};
#pragma unroll
            for (int nt = 0; nt < 8; nt++) {
                u32 bh0 = Bh[nt * 8 + g][kp + tig];
                u32 bh1 = Bh[nt * 8 + g][kp + tig + 4];
                u32 bl0 = Bl[nt * 8 + g][kp + tig];
                u32 bl1 = Bl[nt * 8 + g][kp + tig + 4];
                mma3(acc[nt], ah, al, bh0, bh1, bl0, bl1);
            }
        }
        __syncthreads();
    }

    const int ra = m0 + 16 * w + g;
    const int rb = ra + 8;
#pragma unroll
    for (int nt = 0; nt < 8; nt++) {
        int col = n0 + nt * 8 + 2 * tig;
        float b0 = bias[col], b1 = bias[col + 1];
        if (ra < M) {
            C[(size_t)ra * N + col]     = acc[nt][0] + b0;
            C[(size_t)ra * N + col + 1] = acc[nt][1] + b1;
        }
        if (rb < M) {
            C[(size_t)rb * N + col]     = acc[nt][2] + b0;
            C[(size_t)rb * N + col + 1] = acc[nt][3] + b1;
        }
    }
}

// ---------------------------------------------------------------------------
// Kernel 3: varlen flash attention, 3x-bf16 m16n8k16.
// Block = (64-query tile, segment, head). 128 threads, 4 warps (R6 shape).
// Q pre-scaled + pre-split into registers once. K/V split at load into
// packed k-pair hi/lo smem (19.4 KB total). PV reuses S fragments directly
// (k16 layout makes the pairing natural — no V row permutation needed).
// ---------------------------------------------------------------------------
__global__ __launch_bounds__(128) void attn_mma_kernel(int n) {
    const int seg = blockIdx.y;
    const int h   = blockIdx.z;
    const int qs  = g_start[seg];
    const int qe  = g_start[seg + 1];
    const int q0  = qs + blockIdx.x * 64;
    if (q0 >= qe) return;

    __shared__ u32 Kh[64][20], Kl[64][20];   // [key][hd-pair]
    __shared__ u32 Vh[32][36], Vl[32][36];   // [key-pair][dim], stride 36 (conflict-free)

    const int t    = threadIdx.x;
    const int lane = t & 31, w = t >> 5;
    const int g    = lane >> 2, tig = lane & 3;

    const float* __restrict__ qkv = g_qkv;
    const int qoff = h * 96;
    const int koff = h * 96 + 32;
    const int voff = h * 96 + 64;

    const float scale = 0.17677669529663687f;   // 1/sqrt(32), folded into Q

    // Q fragments: scaled + split once into registers (2 k16-steps over HDIM)
    u32 qh[2][4], ql[2][4];
    {
        int ra = min(q0 + 16 * w + g,     qe - 1);
        int rb = min(q0 + 16 * w + g + 8, qe - 1);
        const float* pa = qkv + (size_t)ra * QKV_DIM + qoff;
        const float* pb = qkv + (size_t)rb * QKV_DIM + qoff;
#pragma unroll
        for (int s = 0; s < 2; s++) {
            float2 a0 = *(const float2*)(pa + 16 * s + 2 * tig);
            float2 b0 = *(const float2*)(pb + 16 * s + 2 * tig);
            float2 a1 = *(const float2*)(pa + 16 * s + 8 + 2 * tig);
            float2 b1 = *(const float2*)(pb + 16 * s + 8 + 2 * tig);
            split2(a0.x * scale, a0.y * scale, qh[s][0], ql[s][0]);
            split2(b0.x * scale, b0.y * scale, qh[s][1], ql[s][1]);
            split2(a1.x * scale, a1.y * scale, qh[s][2], ql[s][2]);
            split2(b1.x * scale, b1.y * scale, qh[s][3], ql[s][3]);
        }
    }

    // loaders: K: row = t>>1, 16-float slab; V: key-pair = t>>2, 8-dim slab
    const int klr = t >> 1, kps = (t & 1) * 8;
    const int vkp = t >> 2, vd0 = (t & 3) * 8;

    float m_a = -1e30f, m_b = -1e30f;
    float l_a = 0.f, l_b = 0.f;
    float out[4][4];
#pragma unroll
    for (int i = 0; i < 4; i++)
#pragma unroll
        for (int j = 0; j < 4; j++) out[i][j] = 0.f;

    for (int j0 = qs; j0 < qe; j0 += 64) {
        const int nk = min(64, qe - j0);
        // ---- K load+split ----
        {
            int row = min(j0 + klr, qe - 1);
            const float* kp_ = qkv + (size_t)row * QKV_DIM + koff + (t & 1) * 16;
#pragma unroll
            for (int q = 0; q < 4; q++) {
                float4 v = *(const float4*)(kp_ + q * 4);
                split2(v.x, v.y, Kh[klr][kps + 2 * q],     Kl[klr][kps + 2 * q]);
                split2(v.z, v.w, Kh[klr][kps + 2 * q + 1], Kl[klr][kps + 2 * q + 1]);
            }
        }
        // ---- V load+split (pairs across adjacent keys, per dim) ----
        {
            int r0 = min(j0 + 2 * vkp,     qe - 1);
            int r1 = min(j0 + 2 * vkp + 1, qe - 1);
            const float* v0p = qkv + (size_t)r0 * QKV_DIM + voff + vd0;
            const float* v1p = qkv + (size_t)r1 * QKV_DIM + voff + vd0;
            float4 x0 = *(const float4*)v0p,       x1 = *(const float4*)(v0p + 4);
            float4 y0 = *(const float4*)v1p,       y1 = *(const float4*)(v1p + 4);
            const float xa[8] = {x0.x, x0.y, x0.z, x0.w, x1.x, x1.y, x1.z, x1.w};
            const float ya[8] = {y0.x, y0.y, y0.z, y0.w, y1.x, y1.y, y1.z, y1.w};
#pragma unroll
            for (int d = 0; d < 8; d++)
                split2(xa[d], ya[d], Vh[vkp][vd0 + d], Vl[vkp][vd0 + d]);
        }
        __syncthreads();

        // ---- S = (Q*scale) @ K^T, 8 key-tiles, 2 k16-steps ----
        float S[8][4];
#pragma unroll
        for (int i = 0; i < 8; i++)
#pragma unroll
            for (int j = 0; j < 4; j++) S[i][j] = 0.f;

#pragma unroll
        for (int s = 0; s < 2; s++) {
            const int kp = s * 8;
#pragma unroll
            for (int nt = 0; nt < 8; nt++) {
                u32 bh0 = Kh[nt * 8 + g][kp + tig];
                u32 bh1 = Kh[nt * 8 + g][kp + tig + 4];
                u32 bl0 = Kl[nt * 8 + g][kp + tig];
                u32 bl1 = Kl[nt * 8 + g][kp + tig + 4];
                mma3(S[nt], qh[s], ql[s], bh0, bh1, bl0, bl1);
            }
        }

        // key mask (scale already folded into Q)
#pragma unroll
        for (int nt = 0; nt < 8; nt++) {
            int c0 = nt * 8 + 2 * tig;
            bool ok0 = c0 < nk, ok1 = (c0 + 1) < nk;
            S[nt][0] = ok0 ? S[nt][0] : -1e30f;
            S[nt][1] = ok1 ? S[nt][1] : -1e30f;
            S[nt][2] = ok0 ? S[nt][2] : -1e30f;
            S[nt][3] = ok1 ? S[nt][3] : -1e30f;
        }

        // row max (4 threads/row share: xor 1,2)
        float ca = -1e30f, cb = -1e30f;
#pragma unroll
        for (int nt = 0; nt < 8; nt++) {
            ca = fmaxf(ca, fmaxf(S[nt][0], S[nt][1]));
            cb = fmaxf(cb, fmaxf(S[nt][2], S[nt][3]));
        }
#pragma unroll
        for (int d = 1; d <= 2; d <<= 1) {
            ca = fmaxf(ca, __shfl_xor_sync(0xffffffffu, ca, d));
            cb = fmaxf(cb, __shfl_xor_sync(0xffffffffu, cb, d));
        }
        float mn_a = fmaxf(m_a, ca);
        float mn_b = fmaxf(m_b, cb);
        float sf_a = __expf(m_a - mn_a);
        float sf_b = __expf(m_b - mn_b);
        m_a = mn_a; m_b = mn_b;

        // P = exp(S - m), partial row sums
        float sa = 0.f, sb = 0.f;
#pragma unroll
        for (int nt = 0; nt < 8; nt++) {
            S[nt][0] = __expf(S[nt][0] - mn_a);
            S[nt][1] = __expf(S[nt][1] - mn_a);
            S[nt][2] = __expf(S[nt][2] - mn_b);
            S[nt][3] = __expf(S[nt][3] - mn_b);
            sa += S[nt][0] + S[nt][1];
            sb += S[nt][2] + S[nt][3];
        }
#pragma unroll
        for (int d = 1; d <= 2; d <<= 1) {
            sa += __shfl_xor_sync(0xffffffffu, sa, d);
            sb += __shfl_xor_sync(0xffffffffu, sb, d);
        }
        l_a = l_a * sf_a + sa;
        l_b = l_b * sf_b + sb;
#pragma unroll
        for (int nt = 0; nt < 4; nt++) {
            out[nt][0] *= sf_a; out[nt][1] *= sf_a;
            out[nt][2] *= sf_b; out[nt][3] *= sf_b;
        }

        // ---- out += P @ V. k16 A-frags pack straight from S tile pairs ----
#pragma unroll
        for (int kt = 0; kt < 4; kt++) {       // 16-key tiles
            u32 ah[4], al[4];
            split2(S[2 * kt][0],     S[2 * kt][1],     ah[0], al[0]);
            split2(S[2 * kt][2],     S[2 * kt][3],     ah[1], al[1]);
            split2(S[2 * kt + 1][0], S[2 * kt + 1][1], ah[2], al[2]);
            split2(S[2 * kt + 1][2], S[2 * kt + 1][3], ah[3], al[3]);
#pragma unroll
            for (int nt = 0; nt < 4; nt++) {   // 8-dim tiles (HDIM=32)
                u32 bh0 = Vh[kt * 8 + tig][nt * 8 + g];
                u32 bh1 = Vh[kt * 8 + tig + 4][nt * 8 + g];
                u32 bl0 = Vl[kt * 8 + tig][nt * 8 + g];
                u32 bl1 = Vl[kt * 8 + tig + 4][nt * 8 + g];
                mma3(out[nt], ah, al, bh0, bh1, bl0, bl1);
            }
        }
        __syncthreads();   // before next chunk overwrites K/V tiles
    }

    const float inv_a = 1.0f / l_a;
    const float inv_b = 1.0f / l_b;
    const int ra = q0 + 16 * w + g;
    const int rb = ra + 8;
#pragma unroll
    for (int nt = 0; nt < 4; nt++) {
        int d = nt * 8 + 2 * tig;
        if (ra < qe) {
            float* p = g_att + (size_t)ra * E_DIM + h * HDIM + d;
            p[0] = out[nt][0] * inv_a;
            p[1] = out[nt][1] * inv_a;
        }
        if (rb < qe) {
            float* p = g_att + (size_t)rb * E_DIM + h * HDIM + d;
            p[0] = out[nt][2] * inv_b;
            p[1] = out[nt][3] * inv_b;
        }
    }
}

// ---------------------------------------------------------------------------
extern "C" void kernel_launch(void* const* d_in, const int* in_sizes, int n_in,
                              void* d_out, int out_size) {
    const float* x      = (const float*)d_in[0];
    const int*   ids    = (const int*)  d_in[1];
    const float* qkv_w  = (const float*)d_in[2];
    const float* qkv_b  = (const float*)d_in[3];
    const float* o_w    = (const float*)d_in[4];
    const float* o_b    = (const float*)d_in[5];
    float*       out    = (float*)d_out;
    const int n = in_sizes[1];   // token count

    hist_kernel<<<1, 256>>>(ids, n);

    float* qkv_out = nullptr;
    cudaGetSymbolAddress((void**)&qkv_out, g_qkv);
    float* att_out = nullptr;
    cudaGetSymbolAddress((void**)&att_out, g_att);

    dim3 g_qkv_grid(QKV_DIM / 64, (n + 63) / 64);
    bf16_gemm_kernel<<<g_qkv_grid, 128>>>(x, qkv_w, qkv_b, qkv_out, n, QKV_DIM, IN_DIM);

    dim3 g_attn((n + 63) / 64, NB, NHEAD);
    attn_mma_kernel<<<g_attn, 128>>>(n);

    dim3 g_proj(E_DIM / 64, (n + 63) / 64);
    bf16_gemm_kernel<<<g_proj, 128>>>(att_out, o_w, o_b, out, n, E_DIM, E_DIM);
}

// round 13
// speedup vs baseline: 2.5687x; 1.0510x over previous
#include <cuda_runtime.h>
#include <cuda_bf16.h>
#include <math.h>
#include <cstdint>

#define N_TOK_MAX 11136
#define IN_DIM    256
#define E_DIM     256
#define NHEAD     8
#define HDIM      32
#define NB        16
#define QKV_DIM   768

typedef unsigned int u32;

// Scratch (device globals: allocation-free rule)
__device__ float g_qkv[(size_t)N_TOK_MAX * QKV_DIM];   // [N, 768]
__device__ float g_att[(size_t)N_TOK_MAX * E_DIM];     // [N, 256]
__device__ int   g_start[NB + 1];

// ---- bf16 3x-compensation helpers ------------------------------------------
// Split two fp32 (v0 = lower-k elem, v1 = upper) into packed bf16x2 hi + lo.
__device__ __forceinline__ void split2(float v0, float v1, u32& hi, u32& lo) {
    asm("cvt.rn.bf16x2.f32 %0, %1, %2;" : "=r"(hi) : "f"(v1), "f"(v0));
    float f0 = __uint_as_float(hi << 16);
    float f1 = __uint_as_float(hi & 0xffff0000u);
    asm("cvt.rn.bf16x2.f32 %0, %1, %2;" : "=r"(lo) : "f"(v1 - f1), "f"(v0 - f0));
}

__device__ __forceinline__ void mma16(float* c, const u32* a, u32 b0, u32 b1) {
    asm volatile(
        "mma.sync.aligned.m16n8k16.row.col.f32.bf16.bf16.f32 "
        "{%0,%1,%2,%3}, {%4,%5,%6,%7}, {%8,%9}, {%0,%1,%2,%3};"
        : "+f"(c[0]), "+f"(c[1]), "+f"(c[2]), "+f"(c[3])
        : "r"(a[0]), "r"(a[1]), "r"(a[2]), "r"(a[3]), "r"(b0), "r"(b1));
}

// 3x-bf16: C += Ahi*Bhi + Ahi*Blo + Alo*Bhi
__device__ __forceinline__ void mma3(float* c, const u32* ah, const u32* al,
                                     u32 bh0, u32 bh1, u32 bl0, u32 bl1) {
    mma16(c, ah, bh0, bh1);
    mma16(c, ah, bl0, bl1);
    mma16(c, al, bh0, bh1);
}

// ---------------------------------------------------------------------------
// Kernel 1: histogram of sorted batch ids -> segment start offsets
// ---------------------------------------------------------------------------
__global__ void hist_kernel(const int* __restrict__ ids, int n) {
    __shared__ int cnt[NB];
    int t = threadIdx.x;
    if (t < NB) cnt[t] = 0;
    __syncthreads();
    for (int i = t; i < n; i += blockDim.x)
        atomicAdd(&cnt[ids[i]], 1);
    __syncthreads();
    if (t == 0) {
        int acc = 0;
        for (int v = 0; v < NB; v++) { g_start[v] = acc; acc += cnt[v]; }
        g_start[NB] = acc;
    }
}

// ---------------------------------------------------------------------------
// 3x-bf16 MMA GEMM, software-pipelined: C[M,N] = A[M,K] @ B[N,K]^T + bias[N]
// 64x64 tile, 128 threads. Per chunk: split prefetched regs -> smem, sync,
// issue next chunk's LDG (latency hidden under mma), mma, sync.
// ---------------------------------------------------------------------------
__global__ __launch_bounds__(128) void bf16_gemm_kernel(
    const float* __restrict__ A, const float* __restrict__ Bw,
    const float* __restrict__ bias, float* __restrict__ C,
    int M, int N, int K)
{
    __shared__ u32 Ah[64][20], Al[64][20];   // [row][k-pair], stride 20 (conflict-free)
    __shared__ u32 Bh[64][20], Bl[64][20];

    const int t    = threadIdx.x;
    const int lane = t & 31, w = t >> 5;
    const int g    = lane >> 2, tig = lane & 3;
    const int m0   = blockIdx.y * 64;
    const int n0   = blockIdx.x * 64;

    float acc[8][4];
#pragma unroll
    for (int i = 0; i < 8; i++)
#pragma unroll
        for (int j = 0; j < 4; j++) acc[i][j] = 0.f;

    const int lr  = t >> 1;           // row 0..63
    const int kps = (t & 1) * 8;      // k-pair slab base (8 pairs = 16 floats)

    const float* aBase = A  + (size_t)min(m0 + lr, M - 1) * K + (t & 1) * 16;
    const float* bBase = Bw + (size_t)(n0 + lr) * K + (t & 1) * 16;

    float4 aR[4], bR[4];
#pragma unroll
    for (int q = 0; q < 4; q++) {
        aR[q] = *(const float4*)(aBase + q * 4);
        bR[q] = *(const float4*)(bBase + q * 4);
    }

    for (int kc = 0; kc < K; kc += 32) {
        // split prefetched regs -> smem
#pragma unroll
        for (int q = 0; q < 4; q++) {
            split2(aR[q].x, aR[q].y, Ah[lr][kps + 2 * q],     Al[lr][kps + 2 * q]);
            split2(aR[q].z, aR[q].w, Ah[lr][kps + 2 * q + 1], Al[lr][kps + 2 * q + 1]);
            split2(bR[q].x, bR[q].y, Bh[lr][kps + 2 * q],     Bl[lr][kps + 2 * q]);
            split2(bR[q].z, bR[q].w, Bh[lr][kps + 2 * q + 1], Bl[lr][kps + 2 * q + 1]);
        }
        __syncthreads();

        // issue next chunk's loads; latency hides under the mma below
        if (kc + 32 < K) {
#pragma unroll
            for (int q = 0; q < 4; q++) {
                aR[q] = *(const float4*)(aBase + kc + 32 + q * 4);
                bR[q] = *(const float4*)(bBase + kc + 32 + q * 4);
            }
        }

#pragma unroll
        for (int s = 0; s < 2; s++) {        // two k16 steps per 32-chunk
            const int kp = s * 8;
            u32 ah[4] = {Ah[16 * w + g][kp + tig],     Ah[16 * w + g + 8][kp + tig],
                         Ah[16 * w + g][kp + tig + 4], Ah[16 * w + g + 8][kp + tig + 4]};
            u32 al[4] = {Al[16 * w + g][kp + tig],     Al[16 * w + g + 8][kp + tig],
                         Al[16 * w + g][kp + tig + 4], Al[16 * w + g + 8][kp + tig + 4]};
#pragma unroll
            for (int nt = 0; nt < 8; nt++) {
                u32 bh0 = Bh[nt * 8 + g][kp + tig];
                u32 bh1 = Bh[nt * 8 + g][kp + tig + 4];
                u32 bl0 = Bl[nt * 8 + g][kp + tig];
                u32 bl1 = Bl[nt * 8 + g][kp + tig + 4];
                mma3(acc[nt], ah, al, bh0, bh1, bl0, bl1);
            }
        }
        __syncthreads();
    }

    const int ra = m0 + 16 * w + g;
    const int rb = ra + 8;
#pragma unroll
    for (int nt = 0; nt < 8; nt++) {
        int col = n0 + nt * 8 + 2 * tig;
        float b0 = bias[col], b1 = bias[col + 1];
        if (ra < M) {
            C[(size_t)ra * N + col]     = acc[nt][0] + b0;
            C[(size_t)ra * N + col + 1] = acc[nt][1] + b1;
        }
        if (rb < M) {
            C[(size_t)rb * N + col]     = acc[nt][2] + b0;
            C[(size_t)rb * N + col + 1] = acc[nt][3] + b1;
        }
    }
}

// ---------------------------------------------------------------------------
// Kernel 3: varlen flash attention, 3x-bf16 m16n8k16, software-pipelined.
// Block = (64-query tile, segment, head). 128 threads, 4 warps.
// Q pre-scaled + pre-split into registers once. K/V prefetched into regs one
// chunk ahead; split at store. PV reuses S fragments directly (k16 pairing).
// ---------------------------------------------------------------------------
__global__ __launch_bounds__(128) void attn_mma_kernel(int n) {
    const int seg = blockIdx.y;
    const int h   = blockIdx.z;
    const int qs  = g_start[seg];
    const int qe  = g_start[seg + 1];
    const int q0  = qs + blockIdx.x * 64;
    if (q0 >= qe) return;

    __shared__ u32 Kh[64][20], Kl[64][20];   // [key][hd-pair]
    __shared__ u32 Vh[32][36], Vl[32][36];   // [key-pair][dim], stride 36

    const int t    = threadIdx.x;
    const int lane = t & 31, w = t >> 5;
    const int g    = lane >> 2, tig = lane & 3;

    const float* __restrict__ qkv = g_qkv;
    const int qoff = h * 96;
    const int koff = h * 96 + 32;
    const int voff = h * 96 + 64;

    const float scale = 0.17677669529663687f;   // 1/sqrt(32), folded into Q

    // Q fragments: scaled + split once into registers (2 k16-steps over HDIM)
    u32 qh[2][4], ql[2][4];
    {
        int ra = min(q0 + 16 * w + g,     qe - 1);
        int rb = min(q0 + 16 * w + g + 8, qe - 1);
        const float* pa = qkv + (size_t)ra * QKV_DIM + qoff;
        const float* pb = qkv + (size_t)rb * QKV_DIM + qoff;
#pragma unroll
        for (int s = 0; s < 2; s++) {
            float2 a0 = *(const float2*)(pa + 16 * s + 2 * tig);
            float2 b0 = *(const float2*)(pb + 16 * s + 2 * tig);
            float2 a1 = *(const float2*)(pa + 16 * s + 8 + 2 * tig);
            float2 b1 = *(const float2*)(pb + 16 * s + 8 + 2 * tig);
            split2(a0.x * scale, a0.y * scale, qh[s][0], ql[s][0]);
            split2(b0.x * scale, b0.y * scale, qh[s][1], ql[s][1]);
            split2(a1.x * scale, a1.y * scale, qh[s][2], ql[s][2]);
            split2(b1.x * scale, b1.y * scale, qh[s][3], ql[s][3]);
        }
    }

    // loaders: K: row = t>>1, 16-float slab; V: key-pair = t>>2, 8-dim slab
    const int klr = t >> 1, kps = (t & 1) * 8;
    const int vkp = t >> 2, vd0 = (t & 3) * 8;

    // prefetch first chunk into regs
    float4 kR[4], vxR[2], vyR[2];
    {
        int rowk = min(qs + klr, qe - 1);
        const float* kp_ = qkv + (size_t)rowk * QKV_DIM + koff + (t & 1) * 16;
#pragma unroll
        for (int q = 0; q < 4; q++) kR[q] = *(const float4*)(kp_ + q * 4);
        int r0 = min(qs + 2 * vkp,     qe - 1);
        int r1 = min(qs + 2 * vkp + 1, qe - 1);
        const float* v0p = qkv + (size_t)r0 * QKV_DIM + voff + vd0;
        const float* v1p = qkv + (size_t)r1 * QKV_DIM + voff + vd0;
        vxR[0] = *(const float4*)v0p; vxR[1] = *(const float4*)(v0p + 4);
        vyR[0] = *(const float4*)v1p; vyR[1] = *(const float4*)(v1p + 4);
    }

    float m_a = -1e30f, m_b = -1e30f;
    float l_a = 0.f, l_b = 0.f;
    float out[4][4];
#pragma unroll
    for (int i = 0; i < 4; i++)
#pragma unroll
        for (int j = 0; j < 4; j++) out[i][j] = 0.f;

    for (int j0 = qs; j0 < qe; j0 += 64) {
        const int nk = min(64, qe - j0);
        // ---- split prefetched K/V regs -> smem ----
#pragma unroll
        for (int q = 0; q < 4; q++) {
            split2(kR[q].x, kR[q].y, Kh[klr][kps + 2 * q],     Kl[klr][kps + 2 * q]);
            split2(kR[q].z, kR[q].w, Kh[klr][kps + 2 * q + 1], Kl[klr][kps + 2 * q + 1]);
        }
        {
            const float xa[8] = {vxR[0].x, vxR[0].y, vxR[0].z, vxR[0].w,
                                 vxR[1].x, vxR[1].y, vxR[1].z, vxR[1].w};
            const float ya[8] = {vyR[0].x, vyR[0].y, vyR[0].z, vyR[0].w,
                                 vyR[1].x, vyR[1].y, vyR[1].z, vyR[1].w};
#pragma unroll
            for (int d = 0; d < 8; d++)
                split2(xa[d], ya[d], Vh[vkp][vd0 + d], Vl[vkp][vd0 + d]);
        }
        __syncthreads();

        // ---- issue next chunk's loads (latency hidden under mma/softmax) ----
        if (j0 + 64 < qe) {
            int rowk = min(j0 + 64 + klr, qe - 1);
            const float* kp_ = qkv + (size_t)rowk * QKV_DIM + koff + (t & 1) * 16;
#pragma unroll
            for (int q = 0; q < 4; q++) kR[q] = *(const float4*)(kp_ + q * 4);
            int r0 = min(j0 + 64 + 2 * vkp,     qe - 1);
            int r1 = min(j0 + 64 + 2 * vkp + 1, qe - 1);
            const float* v0p = qkv + (size_t)r0 * QKV_DIM + voff + vd0;
            const float* v1p = qkv + (size_t)r1 * QKV_DIM + voff + vd0;
            vxR[0] = *(const float4*)v0p; vxR[1] = *(const float4*)(v0p + 4);
            vyR[0] = *(const float4*)v1p; vyR[1] = *(const float4*)(v1p + 4);
        }

        // ---- S = (Q*scale) @ K^T, 8 key-tiles, 2 k16-steps ----
        float S[8][4];
#pragma unroll
        for (int i = 0; i < 8; i++)
#pragma unroll
            for (int j = 0; j < 4; j++) S[i][j] = 0.f;

#pragma unroll
        for (int s = 0; s < 2; s++) {
            const int kp = s * 8;
#pragma unroll
            for (int nt = 0; nt < 8; nt++) {
                u32 bh0 = Kh[nt * 8 + g][kp + tig];
                u32 bh1 = Kh[nt * 8 + g][kp + tig + 4];
                u32 bl0 = Kl[nt * 8 + g][kp + tig];
                u32 bl1 = Kl[nt * 8 + g][kp + tig + 4];
                mma3(S[nt], qh[s], ql[s], bh0, bh1, bl0, bl1);
            }
        }

        // key mask (scale already folded into Q)
#pragma unroll
        for (int nt = 0; nt < 8; nt++) {
            int c0 = nt * 8 + 2 * tig;
            bool ok0 = c0 < nk, ok1 = (c0 + 1) < nk;
            S[nt][0] = ok0 ? S[nt][0] : -1e30f;
            S[nt][1] = ok1 ? S[nt][1] : -1e30f;
            S[nt][2] = ok0 ? S[nt][2] : -1e30f;
            S[nt][3] = ok1 ? S[nt][3] : -1e30f;
        }

        // row max (4 threads/row share: xor 1,2)
        float ca = -1e30f, cb = -1e30f;
#pragma unroll
        for (int nt = 0; nt < 8; nt++) {
            ca = fmaxf(ca, fmaxf(S[nt][0], S[nt][1]));
            cb = fmaxf(cb, fmaxf(S[nt][2], S[nt][3]));
        }
#pragma unroll
        for (int d = 1; d <= 2; d <<= 1) {
            ca = fmaxf(ca, __shfl_xor_sync(0xffffffffu, ca, d));
            cb = fmaxf(cb, __shfl_xor_sync(0xffffffffu, cb, d));
        }
        float mn_a = fmaxf(m_a, ca);
        float mn_b = fmaxf(m_b, cb);
        float sf_a = __expf(m_a - mn_a);
        float sf_b = __expf(m_b - mn_b);
        m_a = mn_a; m_b = mn_b;

        // P = exp(S - m), partial row sums
        float sa = 0.f, sb = 0.f;
#pragma unroll
        for (int nt = 0; nt < 8; nt++) {
            S[nt][0] = __expf(S[nt][0] - mn_a);
            S[nt][1] = __expf(S[nt][1] - mn_a);
            S[nt][2] = __expf(S[nt][2] - mn_b);
            S[nt][3] = __expf(S[nt][3] - mn_b);
            sa += S[nt][0] + S[nt][1];
            sb += S[nt][2] + S[nt][3];
        }
#pragma unroll
        for (int d = 1; d <= 2; d <<= 1) {
            sa += __shfl_xor_sync(0xffffffffu, sa, d);
            sb += __shfl_xor_sync(0xffffffffu, sb, d);
        }
        l_a = l_a * sf_a + sa;
        l_b = l_b * sf_b + sb;
#pragma unroll
        for (int nt = 0; nt < 4; nt++) {
            out[nt][0] *= sf_a; out[nt][1] *= sf_a;
            out[nt][2] *= sf_b; out[nt][3] *= sf_b;
        }

        // ---- out += P @ V. k16 A-frags pack straight from S tile pairs ----
#pragma unroll
        for (int kt = 0; kt < 4; kt++) {       // 16-key tiles
            u32 ah[4], al[4];
            split2(S[2 * kt][0],     S[2 * kt][1],     ah[0], al[0]);
            split2(S[2 * kt][2],     S[2 * kt][3],     ah[1], al[1]);
            split2(S[2 * kt + 1][0], S[2 * kt + 1][1], ah[2], al[2]);
            split2(S[2 * kt + 1][2], S[2 * kt + 1][3], ah[3], al[3]);
#pragma unroll
            for (int nt = 0; nt < 4; nt++) {   // 8-dim tiles (HDIM=32)
                u32 bh0 = Vh[kt * 8 + tig][nt * 8 + g];
                u32 bh1 = Vh[kt * 8 + tig + 4][nt * 8 + g];
                u32 bl0 = Vl[kt * 8 + tig][nt * 8 + g];
                u32 bl1 = Vl[kt * 8 + tig + 4][nt * 8 + g];
                mma3(out[nt], ah, al, bh0, bh1, bl0, bl1);
            }
        }
        __syncthreads();   // before next chunk overwrites K/V tiles
    }

    const float inv_a = 1.0f / l_a;
    const float inv_b = 1.0f / l_b;
    const int ra = q0 + 16 * w + g;
    const int rb = ra + 8;
#pragma unroll
    for (int nt = 0; nt < 4; nt++) {
        int d = nt * 8 + 2 * tig;
        if (ra < qe) {
            float* p = g_att + (size_t)ra * E_DIM + h * HDIM + d;
            p[0] = out[nt][0] * inv_a;
            p[1] = out[nt][1] * inv_a;
        }
        if (rb < qe) {
            float* p = g_att + (size_t)rb * E_DIM + h * HDIM + d;
            p[0] = out[nt][2] * inv_b;
            p[1] = out[nt][3] * inv_b;
        }
    }
}

// ---------------------------------------------------------------------------
extern "C" void kernel_launch(void* const* d_in, const int* in_sizes, int n_in,
                              void* d_out, int out_size) {
    const float* x      = (const float*)d_in[0];
    const int*   ids    = (const int*)  d_in[1];
    const float* qkv_w  = (const float*)d_in[2];
    const float* qkv_b  = (const float*)d_in[3];
    const float* o_w    = (const float*)d_in[4];
    const float* o_b    = (const float*)d_in[5];
    float*       out    = (float*)d_out;
    const int n = in_sizes[1];   // token count

    hist_kernel<<<1, 256>>>(ids, n);

    float* qkv_out = nullptr;
    cudaGetSymbolAddress((void**)&qkv_out, g_qkv);
    float* att_out = nullptr;
    cudaGetSymbolAddress((void**)&att_out, g_att);

    dim3 g_qkv_grid(QKV_DIM / 64, (n + 63) / 64);
    bf16_gemm_kernel<<<g_qkv_grid, 128>>>(x, qkv_w, qkv_b, qkv_out, n, QKV_DIM, IN_DIM);

    dim3 g_attn((n + 63) / 64, NB, NHEAD);
    attn_mma_kernel<<<g_attn, 128>>>(n);

    dim3 g_proj(E_DIM / 64, (n + 63) / 64);
    bf16_gemm_kernel<<<g_proj, 128>>>(att_out, o_w, o_b, out, n, E_DIM, E_DIM);
}